// round 16
// baseline (speedup 1.0000x reference)
#include <cuda_runtime.h>
#include <cuda_fp16.h>
#include <math.h>

#define NNODES 50000
#define NEDGES 800000
#define FEAT   120

// Scratch (static __device__ arrays — allocation-free per harness rules)
__device__ __half2 g_qWh[(size_t)NNODES * FEAT * 2]; // [n][f][4 heads as 2x half2], 48 MB
__device__ __half  g_kh [(size_t)NNODES * FEAT];     // 12 MB
__device__ __half  g_vh [(size_t)NNODES * FEAT];     // 12 MB (fp16 v)
__device__ float   g_z  [NNODES];
// dst-sorted edge list
__device__ int g_cnt [NNODES];
__device__ int g_cur [NNODES];
__device__ int g_off [NNODES + 1];
__device__ int g_ssrc[NEDGES];
__device__ int g_sdst[NEDGES];

__device__ __forceinline__ void store_qw(int n, int f, float4 a, float c) {
    __half2 h01 = __floats2half2_rn(a.x * c, a.y * c);
    __half2 h23 = __floats2half2_rn(a.z * c, a.w * c);
    uint2 u;
    u.x = *reinterpret_cast<unsigned*>(&h01);
    u.y = *reinterpret_cast<unsigned*>(&h23);
    reinterpret_cast<uint2*>(g_qWh)[(size_t)n * FEAT + f] = u;
}

// ---------------------------------------------------------------------------
// Node kernel (R15 verbatim): one warp per 2 nodes, 8 warps/block.
// 50000 = 16 * 3125 exactly -> no bounds checks.
// ---------------------------------------------------------------------------
__global__ __launch_bounds__(256) void node_kernel(
    const float* __restrict__ x,
    const float* __restrict__ Wq0, const float* __restrict__ Wq1, const float* __restrict__ Wq2,
    const float* __restrict__ Wk0, const float* __restrict__ Wk1, const float* __restrict__ Wk2,
    const float* __restrict__ Wv0, const float* __restrict__ Wv1, const float* __restrict__ Wv2,
    const float* __restrict__ Wd0, const float* __restrict__ Wd1, const float* __restrict__ Wd2,
    float* __restrict__ out)
{
    __shared__ float sX[8][2][FEAT];
    __shared__ float sQ[8][2][FEAT];

    const int warp = threadIdx.x >> 5;
    const int lane = threadIdx.x & 31;
    const int n0 = blockIdx.x * 16 + warp * 2;
    const int n1 = n0 + 1;

    float* xs0 = sX[warp][0];
    float* xs1 = sX[warp][1];
    float* qs0 = sQ[warp][0];
    float* qs1 = sQ[warp][1];

    for (int f = lane; f < FEAT; f += 32) {
        xs0[f] = x[(size_t)n0 * FEAT + f];
        xs1[f] = x[(size_t)n1 * FEAT + f];
        out[(size_t)n0 * FEAT + f] = 0.0f;   // out accumulates edge sums
        out[(size_t)n1 * FEAT + f] = 0.0f;
    }
    if (lane == 0) { g_z[n0] = 0.0f; g_z[n1] = 0.0f; }
    __syncwarp();

    const float inv_s32 = 0.1767766953f;   // 1/sqrt(32)
    const float inv_s16 = 0.25f;
    const float inv_s8  = 0.3535533906f;   // 1/sqrt(8)

    __half* kp0 = g_kh + (size_t)n0 * FEAT;
    __half* kp1 = g_kh + (size_t)n1 * FEAT;
    __half* vp0 = g_vh + (size_t)n0 * FEAT;
    __half* vp1 = g_vh + (size_t)n1 * FEAT;

    #pragma unroll 1
    for (int pass = 0; pass < 3; ++pass) {
        const float* W0 = (pass == 0) ? Wq0 : ((pass == 1) ? Wk0 : Wv0);
        const float* W1 = (pass == 0) ? Wq1 : ((pass == 1) ? Wk1 : Wv1);
        const float* W2 = (pass == 0) ? Wq2 : ((pass == 1) ? Wk2 : Wv2);

        // l=0: output j = lane
        {
            float a0 = 0.f, a1 = 0.f;
            #pragma unroll
            for (int i = 0; i < 32; ++i) {
                float w = __ldg(&W0[i * 32 + lane]);
                a0 += xs0[i] * w;
                a1 += xs1[i] * w;
            }
            a0 *= inv_s32; a1 *= inv_s32;
            float nn0 = sqrtf(a0*a0 + 1e-10f), nn1 = sqrtf(a1*a1 + 1e-10f);
            float y0 = (1.0f / (1.0f + __expf(-nn0))) / nn0 * a0;
            float y1 = (1.0f / (1.0f + __expf(-nn1))) / nn1 * a1;
            if (pass == 0)      { qs0[lane] = y0; qs1[lane] = y1; }
            else if (pass == 1) { kp0[lane] = __float2half_rn(y0); kp1[lane] = __float2half_rn(y1); }
            else                { vp0[lane] = __float2half_rn(y0); vp1[lane] = __float2half_rn(y1); }
        }
        // l=1: lanes 0..15, output j = lane
        if (lane < 16) {
            float r0[3], r1[3];
            #pragma unroll
            for (int m = 0; m < 3; ++m) { r0[m] = 0.f; r1[m] = 0.f; }
            #pragma unroll
            for (int i = 0; i < 16; ++i) {
                float w = __ldg(&W1[i * 16 + lane]);
                #pragma unroll
                for (int m = 0; m < 3; ++m) {
                    r0[m] += xs0[32 + i*3 + m] * w;
                    r1[m] += xs1[32 + i*3 + m] * w;
                }
            }
            float ss0 = 0.f, ss1 = 0.f;
            #pragma unroll
            for (int m = 0; m < 3; ++m) {
                r0[m] *= inv_s16; r1[m] *= inv_s16;
                ss0 += r0[m]*r0[m]; ss1 += r1[m]*r1[m];
            }
            float nn0 = sqrtf(ss0 + 1e-10f), nn1 = sqrtf(ss1 + 1e-10f);
            float sc0 = (1.0f / (1.0f + __expf(-nn0))) / nn0;
            float sc1 = (1.0f / (1.0f + __expf(-nn1))) / nn1;
            #pragma unroll
            for (int m = 0; m < 3; ++m) {
                int f = 32 + lane*3 + m;
                float y0 = sc0 * r0[m], y1 = sc1 * r1[m];
                if (pass == 0)      { qs0[f] = y0; qs1[f] = y1; }
                else if (pass == 1) { kp0[f] = __float2half_rn(y0); kp1[f] = __float2half_rn(y1); }
                else                { vp0[f] = __float2half_rn(y0); vp1[f] = __float2half_rn(y1); }
            }
        }
        // l=2: lanes 16..23, output j = lane-16
        else if (lane < 24) {
            const int j = lane - 16;
            float r0[5], r1[5];
            #pragma unroll
            for (int m = 0; m < 5; ++m) { r0[m] = 0.f; r1[m] = 0.f; }
            #pragma unroll
            for (int i = 0; i < 8; ++i) {
                float w = __ldg(&W2[i * 8 + j]);
                #pragma unroll
                for (int m = 0; m < 5; ++m) {
                    r0[m] += xs0[80 + i*5 + m] * w;
                    r1[m] += xs1[80 + i*5 + m] * w;
                }
            }
            float ss0 = 0.f, ss1 = 0.f;
            #pragma unroll
            for (int m = 0; m < 5; ++m) {
                r0[m] *= inv_s8; r1[m] *= inv_s8;
                ss0 += r0[m]*r0[m]; ss1 += r1[m]*r1[m];
            }
            float nn0 = sqrtf(ss0 + 1e-10f), nn1 = sqrtf(ss1 + 1e-10f);
            float sc0 = (1.0f / (1.0f + __expf(-nn0))) / nn0;
            float sc1 = (1.0f / (1.0f + __expf(-nn1))) / nn1;
            #pragma unroll
            for (int m = 0; m < 5; ++m) {
                int f = 80 + j*5 + m;
                float y0 = sc0 * r0[m], y1 = sc1 * r1[m];
                if (pass == 0)      { qs0[f] = y0; qs1[f] = y1; }
                else if (pass == 1) { kp0[f] = __float2half_rn(y0); kp1[f] = __float2half_rn(y1); }
                else                { vp0[f] = __float2half_rn(y0); vp1[f] = __float2half_rn(y1); }
            }
        }
        __syncwarp();
    }

    // ---- Wd contraction: qW[n][f][4], both nodes share every Wd wavefront ----
    const float c0 = 0.02176061898f;     // 1/sqrt(2112)
    const float c1 = c0 * 0.5773502692f; // c0/sqrt(3)
    const float c2 = c0 * 0.4472135955f; // c0/sqrt(5)
    const float4* D0 = reinterpret_cast<const float4*>(Wd0);
    const float4* D1 = reinterpret_cast<const float4*>(Wd1);
    const float4* D2 = reinterpret_cast<const float4*>(Wd2);

    // l=0: j = lane
    {
        float4 A0 = make_float4(0.f,0.f,0.f,0.f);
        float4 A1 = make_float4(0.f,0.f,0.f,0.f);
        #pragma unroll
        for (int i = 0; i < 32; ++i) {
            float4 w = __ldg(&D0[i * 32 + lane]);
            float q0 = qs0[i], q1 = qs1[i];
            A0.x += q0*w.x; A0.y += q0*w.y; A0.z += q0*w.z; A0.w += q0*w.w;
            A1.x += q1*w.x; A1.y += q1*w.y; A1.z += q1*w.z; A1.w += q1*w.w;
        }
        store_qw(n0, lane, A0, c0);
        store_qw(n1, lane, A1, c0);
    }
    // l=1: lanes 0..15, j = lane
    if (lane < 16) {
        float4 B0[3], B1[3];
        #pragma unroll
        for (int m = 0; m < 3; ++m) {
            B0[m] = make_float4(0.f,0.f,0.f,0.f);
            B1[m] = make_float4(0.f,0.f,0.f,0.f);
        }
        #pragma unroll
        for (int i = 0; i < 16; ++i) {
            float4 w = __ldg(&D1[i * 16 + lane]);
            #pragma unroll
            for (int m = 0; m < 3; ++m) {
                float q0 = qs0[32 + i*3 + m], q1 = qs1[32 + i*3 + m];
                B0[m].x += q0*w.x; B0[m].y += q0*w.y; B0[m].z += q0*w.z; B0[m].w += q0*w.w;
                B1[m].x += q1*w.x; B1[m].y += q1*w.y; B1[m].z += q1*w.z; B1[m].w += q1*w.w;
            }
        }
        #pragma unroll
        for (int m = 0; m < 3; ++m) {
            int f = 32 + lane*3 + m;
            store_qw(n0, f, B0[m], c1);
            store_qw(n1, f, B1[m], c1);
        }
    }
    // l=2: lanes 16..23, j = lane-16
    else if (lane < 24) {
        const int j = lane - 16;
        float4 C0[5], C1[5];
        #pragma unroll
        for (int m = 0; m < 5; ++m) {
            C0[m] = make_float4(0.f,0.f,0.f,0.f);
            C1[m] = make_float4(0.f,0.f,0.f,0.f);
        }
        #pragma unroll
        for (int i = 0; i < 8; ++i) {
            float4 w = __ldg(&D2[i * 8 + j]);
            #pragma unroll
            for (int m = 0; m < 5; ++m) {
                float q0 = qs0[80 + i*5 + m], q1 = qs1[80 + i*5 + m];
                C0[m].x += q0*w.x; C0[m].y += q0*w.y; C0[m].z += q0*w.z; C0[m].w += q0*w.w;
                C1[m].x += q1*w.x; C1[m].y += q1*w.y; C1[m].z += q1*w.z; C1[m].w += q1*w.w;
            }
        }
        #pragma unroll
        for (int m = 0; m < 5; ++m) {
            int f = 80 + j*5 + m;
            store_qw(n0, f, C0[m], c2);
            store_qw(n1, f, C1[m], c2);
        }
    }
}

// ---------------------------------------------------------------------------
// Binning kernels (dst-sorted edge list)
// ---------------------------------------------------------------------------
__global__ void zero_cnt_kernel() {
    int i = blockIdx.x * blockDim.x + threadIdx.x;
    if (i < NNODES) g_cnt[i] = 0;
}

__global__ void hist_kernel(const int* __restrict__ dsts) {
    int e = blockIdx.x * blockDim.x + threadIdx.x;
    if (e < NEDGES) atomicAdd(&g_cnt[dsts[e]], 1);
}

__global__ __launch_bounds__(1024) void scan_kernel() {
    __shared__ int sp[1024];
    const int t = threadIdx.x;
    const int CH = (NNODES + 1023) / 1024;          // 49
    const int beg = t * CH;
    const int end = (beg + CH < NNODES) ? beg + CH : NNODES;

    int sum = 0;
    for (int i = beg; i < end; ++i) sum += g_cnt[i];
    sp[t] = sum;
    __syncthreads();
    for (int d = 1; d < 1024; d <<= 1) {
        int v = (t >= d) ? sp[t - d] : 0;
        __syncthreads();
        sp[t] += v;
        __syncthreads();
    }
    int run = (t > 0) ? sp[t - 1] : 0;
    for (int i = beg; i < end; ++i) {
        g_off[i] = run;
        g_cur[i] = run;
        run += g_cnt[i];
    }
    if (end == NNODES && beg < NNODES) g_off[NNODES] = run;
}

__global__ void scatter_kernel(const int* __restrict__ dsts, const int* __restrict__ srcs) {
    int e = blockIdx.x * blockDim.x + threadIdx.x;
    if (e < NEDGES) {
        int d = dsts[e];
        int p = atomicAdd(&g_cur[d], 1);
        g_ssrc[p] = srcs[e];
        g_sdst[p] = d;
    }
}

// ---------------------------------------------------------------------------
// Edge kernel: 8 SORTED edges per block (one warp each). Scores as in R15;
// per-block segmented combine over shared smem removes per-edge REDG/atomics:
// one scalar-REDG run + one z atomic per distinct dst in the block.
// 800000 = 100000 blocks * 8 exactly.
// ---------------------------------------------------------------------------
__global__ __launch_bounds__(256) void edge_kernel(float* __restrict__ out)
{
    __shared__ float sacc[8][FEAT];
    __shared__ int   sd[8];
    __shared__ float sev[8];

    const int warp = threadIdx.x >> 5;
    const int lane = threadIdx.x & 31;
    const int e = blockIdx.x * 8 + warp;
    const int d = g_sdst[e];
    const int s = g_ssrc[e];

    const uint2*  qw = reinterpret_cast<const uint2*>(g_qWh + (size_t)d * FEAT * 2);
    const __half* kk = g_kh + (size_t)s * FEAT;

    float ax = 0.f, ay = 0.f, az = 0.f, aw = 0.f;
    #pragma unroll
    for (int it = 0; it < 4; ++it) {
        int f = lane + it * 32;
        if (f < FEAT) {
            float kf = __half2float(kk[f]);
            uint2 wv = qw[f];
            float2 p01 = __half22float2(*reinterpret_cast<__half2*>(&wv.x));
            float2 p23 = __half22float2(*reinterpret_cast<__half2*>(&wv.y));
            ax += p01.x * kf; ay += p01.y * kf; az += p23.x * kf; aw += p23.y * kf;
        }
    }
    #pragma unroll
    for (int off = 16; off > 0; off >>= 1) {
        ax += __shfl_xor_sync(0xffffffffu, ax, off);
        ay += __shfl_xor_sync(0xffffffffu, ay, off);
        az += __shfl_xor_sync(0xffffffffu, az, off);
        aw += __shfl_xor_sync(0xffffffffu, aw, off);
    }
    const float ev = 0.25f * (__expf(ax) + __expf(ay) + __expf(az) + __expf(aw));
    const float w = sqrtf(ev);

    if (lane == 0) { sd[warp] = d; sev[warp] = ev; }
    if (lane < FEAT / 4) {  // 30 lanes stage sqrt(ev)*v into smem
        uint2 vv = reinterpret_cast<const uint2*>(g_vh + (size_t)s * FEAT)[lane];
        float2 v01 = __half22float2(*reinterpret_cast<__half2*>(&vv.x));
        float2 v23 = __half22float2(*reinterpret_cast<__half2*>(&vv.y));
        *reinterpret_cast<float4*>(&sacc[warp][lane * 4]) =
            make_float4(w * v01.x, w * v01.y, w * v23.x, w * v23.y);
    }
    __syncthreads();

    const int tid = threadIdx.x;
    if (tid < FEAT) {
        // Segmented combine over the block's 8 (sorted) edges, one REDG per group
        float acc = sacc[0][tid];
        int dprev = sd[0];
        #pragma unroll
        for (int wi = 1; wi < 8; ++wi) {
            int dw = sd[wi];
            if (dw == dprev) {
                acc += sacc[wi][tid];
            } else {
                asm volatile("red.global.add.f32 [%0], %1;"
                             :: "l"(out + (size_t)dprev * FEAT + tid), "f"(acc) : "memory");
                acc = sacc[wi][tid];
                dprev = dw;
            }
        }
        asm volatile("red.global.add.f32 [%0], %1;"
                     :: "l"(out + (size_t)dprev * FEAT + tid), "f"(acc) : "memory");
    } else if (tid == 128) {
        float az2 = sev[0];
        int dprev = sd[0];
        #pragma unroll
        for (int wi = 1; wi < 8; ++wi) {
            int dw = sd[wi];
            if (dw == dprev) {
                az2 += sev[wi];
            } else {
                atomicAdd(&g_z[dprev], az2);
                az2 = sev[wi];
                dprev = dw;
            }
        }
        atomicAdd(&g_z[dprev], az2);
    }
}

// ---------------------------------------------------------------------------
// Finalize: out = v_node(fp16) + out * rsqrt(z)   (z==0 -> out sum is 0)
// ---------------------------------------------------------------------------
__global__ __launch_bounds__(256) void finalize_kernel(float* __restrict__ out)
{
    const int t = blockIdx.x * blockDim.x + threadIdx.x;
    if (t >= NNODES * (FEAT / 4)) return;
    const int n = t / (FEAT / 4);
    const float zz = g_z[n];
    const float sc = (zz > 0.0f) ? rsqrtf(zz) : 0.0f;
    float4 o = reinterpret_cast<float4*>(out)[t];
    uint2 vv = reinterpret_cast<const uint2*>(g_vh)[t];
    float2 v01 = __half22float2(*reinterpret_cast<__half2*>(&vv.x));
    float2 v23 = __half22float2(*reinterpret_cast<__half2*>(&vv.y));
    o.x = v01.x + o.x * sc;
    o.y = v01.y + o.y * sc;
    o.z = v23.x + o.z * sc;
    o.w = v23.y + o.w * sc;
    reinterpret_cast<float4*>(out)[t] = o;
}

// ---------------------------------------------------------------------------
extern "C" void kernel_launch(void* const* d_in, const int* in_sizes, int n_in,
                              void* d_out, int out_size)
{
    const float* x   = (const float*)d_in[0];
    const float* Wq0 = (const float*)d_in[1];
    const float* Wq1 = (const float*)d_in[2];
    const float* Wq2 = (const float*)d_in[3];
    const float* Wk0 = (const float*)d_in[4];
    const float* Wk1 = (const float*)d_in[5];
    const float* Wk2 = (const float*)d_in[6];
    const float* Wv0 = (const float*)d_in[7];
    const float* Wv1 = (const float*)d_in[8];
    const float* Wv2 = (const float*)d_in[9];
    const float* Wd0 = (const float*)d_in[10];
    const float* Wd1 = (const float*)d_in[11];
    const float* Wd2 = (const float*)d_in[12];
    const int* edge_dst = (const int*)d_in[13];
    const int* edge_src = (const int*)d_in[14];
    float* out = (float*)d_out;

    // Binning (dst-sorted edge list) — overlaps conceptually with node work
    zero_cnt_kernel<<<(NNODES + 255) / 256, 256>>>();
    hist_kernel<<<(NEDGES + 255) / 256, 256>>>(edge_dst);
    scan_kernel<<<1, 1024>>>();
    scatter_kernel<<<(NEDGES + 255) / 256, 256>>>(edge_dst, edge_src);

    // Node kernel: 16 nodes/block (2 per warp), 50000/16 = 3125 blocks
    node_kernel<<<NNODES / 16, 256>>>(x, Wq0, Wq1, Wq2, Wk0, Wk1, Wk2,
                                      Wv0, Wv1, Wv2, Wd0, Wd1, Wd2, out);

    // Edge kernel: 8 sorted edges/block, block-local segmented aggregation
    edge_kernel<<<NEDGES / 8, 256>>>(out);

    // Finalize: one thread per float4 of out
    const int nt = NNODES * (FEAT / 4);
    finalize_kernel<<<(nt + 255) / 256, 256>>>(out);
}

// round 17
// speedup vs baseline: 1.3511x; 1.3511x over previous
#include <cuda_runtime.h>
#include <cuda_fp16.h>
#include <math.h>

#define NNODES 50000
#define NEDGES 800000
#define FEAT   120

// Scratch (static __device__ arrays — allocation-free per harness rules)
__device__ __half2 g_qWh[(size_t)NNODES * FEAT * 2]; // [n][f][4 heads as 2x half2], 48 MB
__device__ __half  g_kh [(size_t)NNODES * FEAT];     // 12 MB
__device__ __half  g_vh [(size_t)NNODES * FEAT];     // 12 MB (fp16 v, edge gather + finalize)
__device__ float   g_z  [NNODES];

__device__ __forceinline__ void store_qw(int n, int f, float4 a, float c) {
    __half2 h01 = __floats2half2_rn(a.x * c, a.y * c);
    __half2 h23 = __floats2half2_rn(a.z * c, a.w * c);
    uint2 u;
    u.x = *reinterpret_cast<unsigned*>(&h01);
    u.y = *reinterpret_cast<unsigned*>(&h23);
    reinterpret_cast<uint2*>(g_qWh)[(size_t)n * FEAT + f] = u;
}

// ---------------------------------------------------------------------------
// Node kernel (R15 verbatim — pinned local optimum, do not touch):
// one warp per 2 nodes, 8 warps/block. 50000 = 16 * 3125 exactly.
// ---------------------------------------------------------------------------
__global__ __launch_bounds__(256) void node_kernel(
    const float* __restrict__ x,
    const float* __restrict__ Wq0, const float* __restrict__ Wq1, const float* __restrict__ Wq2,
    const float* __restrict__ Wk0, const float* __restrict__ Wk1, const float* __restrict__ Wk2,
    const float* __restrict__ Wv0, const float* __restrict__ Wv1, const float* __restrict__ Wv2,
    const float* __restrict__ Wd0, const float* __restrict__ Wd1, const float* __restrict__ Wd2,
    float* __restrict__ out)
{
    __shared__ float sX[8][2][FEAT];
    __shared__ float sQ[8][2][FEAT];

    const int warp = threadIdx.x >> 5;
    const int lane = threadIdx.x & 31;
    const int n0 = blockIdx.x * 16 + warp * 2;
    const int n1 = n0 + 1;

    float* xs0 = sX[warp][0];
    float* xs1 = sX[warp][1];
    float* qs0 = sQ[warp][0];
    float* qs1 = sQ[warp][1];

    for (int f = lane; f < FEAT; f += 32) {
        xs0[f] = x[(size_t)n0 * FEAT + f];
        xs1[f] = x[(size_t)n1 * FEAT + f];
        out[(size_t)n0 * FEAT + f] = 0.0f;   // out accumulates edge sums
        out[(size_t)n1 * FEAT + f] = 0.0f;
    }
    if (lane == 0) { g_z[n0] = 0.0f; g_z[n1] = 0.0f; }
    __syncwarp();

    const float inv_s32 = 0.1767766953f;   // 1/sqrt(32)
    const float inv_s16 = 0.25f;
    const float inv_s8  = 0.3535533906f;   // 1/sqrt(8)

    __half* kp0 = g_kh + (size_t)n0 * FEAT;
    __half* kp1 = g_kh + (size_t)n1 * FEAT;
    __half* vp0 = g_vh + (size_t)n0 * FEAT;
    __half* vp1 = g_vh + (size_t)n1 * FEAT;

    #pragma unroll 1
    for (int pass = 0; pass < 3; ++pass) {
        const float* W0 = (pass == 0) ? Wq0 : ((pass == 1) ? Wk0 : Wv0);
        const float* W1 = (pass == 0) ? Wq1 : ((pass == 1) ? Wk1 : Wv1);
        const float* W2 = (pass == 0) ? Wq2 : ((pass == 1) ? Wk2 : Wv2);

        // l=0: output j = lane
        {
            float a0 = 0.f, a1 = 0.f;
            #pragma unroll
            for (int i = 0; i < 32; ++i) {
                float w = __ldg(&W0[i * 32 + lane]);
                a0 += xs0[i] * w;
                a1 += xs1[i] * w;
            }
            a0 *= inv_s32; a1 *= inv_s32;
            float nn0 = sqrtf(a0*a0 + 1e-10f), nn1 = sqrtf(a1*a1 + 1e-10f);
            float y0 = (1.0f / (1.0f + __expf(-nn0))) / nn0 * a0;
            float y1 = (1.0f / (1.0f + __expf(-nn1))) / nn1 * a1;
            if (pass == 0)      { qs0[lane] = y0; qs1[lane] = y1; }
            else if (pass == 1) { kp0[lane] = __float2half_rn(y0); kp1[lane] = __float2half_rn(y1); }
            else                { vp0[lane] = __float2half_rn(y0); vp1[lane] = __float2half_rn(y1); }
        }
        // l=1: lanes 0..15, output j = lane
        if (lane < 16) {
            float r0[3], r1[3];
            #pragma unroll
            for (int m = 0; m < 3; ++m) { r0[m] = 0.f; r1[m] = 0.f; }
            #pragma unroll
            for (int i = 0; i < 16; ++i) {
                float w = __ldg(&W1[i * 16 + lane]);
                #pragma unroll
                for (int m = 0; m < 3; ++m) {
                    r0[m] += xs0[32 + i*3 + m] * w;
                    r1[m] += xs1[32 + i*3 + m] * w;
                }
            }
            float ss0 = 0.f, ss1 = 0.f;
            #pragma unroll
            for (int m = 0; m < 3; ++m) {
                r0[m] *= inv_s16; r1[m] *= inv_s16;
                ss0 += r0[m]*r0[m]; ss1 += r1[m]*r1[m];
            }
            float nn0 = sqrtf(ss0 + 1e-10f), nn1 = sqrtf(ss1 + 1e-10f);
            float sc0 = (1.0f / (1.0f + __expf(-nn0))) / nn0;
            float sc1 = (1.0f / (1.0f + __expf(-nn1))) / nn1;
            #pragma unroll
            for (int m = 0; m < 3; ++m) {
                int f = 32 + lane*3 + m;
                float y0 = sc0 * r0[m], y1 = sc1 * r1[m];
                if (pass == 0)      { qs0[f] = y0; qs1[f] = y1; }
                else if (pass == 1) { kp0[f] = __float2half_rn(y0); kp1[f] = __float2half_rn(y1); }
                else                { vp0[f] = __float2half_rn(y0); vp1[f] = __float2half_rn(y1); }
            }
        }
        // l=2: lanes 16..23, output j = lane-16
        else if (lane < 24) {
            const int j = lane - 16;
            float r0[5], r1[5];
            #pragma unroll
            for (int m = 0; m < 5; ++m) { r0[m] = 0.f; r1[m] = 0.f; }
            #pragma unroll
            for (int i = 0; i < 8; ++i) {
                float w = __ldg(&W2[i * 8 + j]);
                #pragma unroll
                for (int m = 0; m < 5; ++m) {
                    r0[m] += xs0[80 + i*5 + m] * w;
                    r1[m] += xs1[80 + i*5 + m] * w;
                }
            }
            float ss0 = 0.f, ss1 = 0.f;
            #pragma unroll
            for (int m = 0; m < 5; ++m) {
                r0[m] *= inv_s8; r1[m] *= inv_s8;
                ss0 += r0[m]*r0[m]; ss1 += r1[m]*r1[m];
            }
            float nn0 = sqrtf(ss0 + 1e-10f), nn1 = sqrtf(ss1 + 1e-10f);
            float sc0 = (1.0f / (1.0f + __expf(-nn0))) / nn0;
            float sc1 = (1.0f / (1.0f + __expf(-nn1))) / nn1;
            #pragma unroll
            for (int m = 0; m < 5; ++m) {
                int f = 80 + j*5 + m;
                float y0 = sc0 * r0[m], y1 = sc1 * r1[m];
                if (pass == 0)      { qs0[f] = y0; qs1[f] = y1; }
                else if (pass == 1) { kp0[f] = __float2half_rn(y0); kp1[f] = __float2half_rn(y1); }
                else                { vp0[f] = __float2half_rn(y0); vp1[f] = __float2half_rn(y1); }
            }
        }
        __syncwarp();
    }

    // ---- Wd contraction: qW[n][f][4], both nodes share every Wd wavefront ----
    const float c0 = 0.02176061898f;     // 1/sqrt(2112)
    const float c1 = c0 * 0.5773502692f; // c0/sqrt(3)
    const float c2 = c0 * 0.4472135955f; // c0/sqrt(5)
    const float4* D0 = reinterpret_cast<const float4*>(Wd0);
    const float4* D1 = reinterpret_cast<const float4*>(Wd1);
    const float4* D2 = reinterpret_cast<const float4*>(Wd2);

    // l=0: j = lane
    {
        float4 A0 = make_float4(0.f,0.f,0.f,0.f);
        float4 A1 = make_float4(0.f,0.f,0.f,0.f);
        #pragma unroll
        for (int i = 0; i < 32; ++i) {
            float4 w = __ldg(&D0[i * 32 + lane]);
            float q0 = qs0[i], q1 = qs1[i];
            A0.x += q0*w.x; A0.y += q0*w.y; A0.z += q0*w.z; A0.w += q0*w.w;
            A1.x += q1*w.x; A1.y += q1*w.y; A1.z += q1*w.z; A1.w += q1*w.w;
        }
        store_qw(n0, lane, A0, c0);
        store_qw(n1, lane, A1, c0);
    }
    // l=1: lanes 0..15, j = lane
    if (lane < 16) {
        float4 B0[3], B1[3];
        #pragma unroll
        for (int m = 0; m < 3; ++m) {
            B0[m] = make_float4(0.f,0.f,0.f,0.f);
            B1[m] = make_float4(0.f,0.f,0.f,0.f);
        }
        #pragma unroll
        for (int i = 0; i < 16; ++i) {
            float4 w = __ldg(&D1[i * 16 + lane]);
            #pragma unroll
            for (int m = 0; m < 3; ++m) {
                float q0 = qs0[32 + i*3 + m], q1 = qs1[32 + i*3 + m];
                B0[m].x += q0*w.x; B0[m].y += q0*w.y; B0[m].z += q0*w.z; B0[m].w += q0*w.w;
                B1[m].x += q1*w.x; B1[m].y += q1*w.y; B1[m].z += q1*w.z; B1[m].w += q1*w.w;
            }
        }
        #pragma unroll
        for (int m = 0; m < 3; ++m) {
            int f = 32 + lane*3 + m;
            store_qw(n0, f, B0[m], c1);
            store_qw(n1, f, B1[m], c1);
        }
    }
    // l=2: lanes 16..23, j = lane-16
    else if (lane < 24) {
        const int j = lane - 16;
        float4 C0[5], C1[5];
        #pragma unroll
        for (int m = 0; m < 5; ++m) {
            C0[m] = make_float4(0.f,0.f,0.f,0.f);
            C1[m] = make_float4(0.f,0.f,0.f,0.f);
        }
        #pragma unroll
        for (int i = 0; i < 8; ++i) {
            float4 w = __ldg(&D2[i * 8 + j]);
            #pragma unroll
            for (int m = 0; m < 5; ++m) {
                float q0 = qs0[80 + i*5 + m], q1 = qs1[80 + i*5 + m];
                C0[m].x += q0*w.x; C0[m].y += q0*w.y; C0[m].z += q0*w.z; C0[m].w += q0*w.w;
                C1[m].x += q1*w.x; C1[m].y += q1*w.y; C1[m].z += q1*w.z; C1[m].w += q1*w.w;
            }
        }
        #pragma unroll
        for (int m = 0; m < 5; ++m) {
            int f = 80 + j*5 + m;
            store_qw(n0, f, C0[m], c2);
            store_qw(n1, f, C1[m], c2);
        }
    }
}

// ---------------------------------------------------------------------------
// Fused edge kernel (R15 lane layout; 512 threads = 16 edges/block,
// 800000 / 16 = 50000 blocks exactly -> no bounds check).
// ev = mean_h exp(qW[dst]·k[src]); z[dst] += ev; out[dst] += sqrt(ev)*v[src].
// ---------------------------------------------------------------------------
__global__ __launch_bounds__(512) void edge_kernel(
    const int* __restrict__ dsts, const int* __restrict__ srcs,
    float* __restrict__ out)
{
    const int e = (blockIdx.x * blockDim.x + threadIdx.x) >> 5;
    const int lane = threadIdx.x & 31;
    const int d = dsts[e];
    const int s = srcs[e];

    const uint2*  qw = reinterpret_cast<const uint2*>(g_qWh + (size_t)d * FEAT * 2);
    const __half* kk = g_kh + (size_t)s * FEAT;

    float ax = 0.f, ay = 0.f, az = 0.f, aw = 0.f;
    #pragma unroll
    for (int it = 0; it < 4; ++it) {
        int f = lane + it * 32;
        if (f < FEAT) {
            float kf = __half2float(kk[f]);
            uint2 wv = qw[f];
            float2 p01 = __half22float2(*reinterpret_cast<__half2*>(&wv.x));
            float2 p23 = __half22float2(*reinterpret_cast<__half2*>(&wv.y));
            ax += p01.x * kf; ay += p01.y * kf; az += p23.x * kf; aw += p23.y * kf;
        }
    }
    #pragma unroll
    for (int off = 16; off > 0; off >>= 1) {
        ax += __shfl_xor_sync(0xffffffffu, ax, off);
        ay += __shfl_xor_sync(0xffffffffu, ay, off);
        az += __shfl_xor_sync(0xffffffffu, az, off);
        aw += __shfl_xor_sync(0xffffffffu, aw, off);
    }
    const float ev = 0.25f * (__expf(ax) + __expf(ay) + __expf(az) + __expf(aw));
    if (lane == 0) atomicAdd(&g_z[d], ev);

    const float w = sqrtf(ev);
    if (lane < FEAT / 4) {  // 30 lanes, float4 chunk f = 4*lane (fp16 source)
        uint2 vv = reinterpret_cast<const uint2*>(g_vh + (size_t)s * FEAT)[lane];
        float2 v01 = __half22float2(*reinterpret_cast<__half2*>(&vv.x));
        float2 v23 = __half22float2(*reinterpret_cast<__half2*>(&vv.y));
        float* p = out + (size_t)d * FEAT + lane * 4;
        asm volatile("red.global.add.v4.f32 [%0], {%1, %2, %3, %4};"
                     :: "l"(p), "f"(w * v01.x), "f"(w * v01.y), "f"(w * v23.x), "f"(w * v23.y)
                     : "memory");
    }
}

// ---------------------------------------------------------------------------
// Finalize: out = v_node(fp16) + out * rsqrt(z)   (z==0 -> out sum is 0)
// ---------------------------------------------------------------------------
__global__ __launch_bounds__(256) void finalize_kernel(float* __restrict__ out)
{
    const int t = blockIdx.x * blockDim.x + threadIdx.x;
    if (t >= NNODES * (FEAT / 4)) return;
    const int n = t / (FEAT / 4);
    const float zz = g_z[n];
    const float sc = (zz > 0.0f) ? rsqrtf(zz) : 0.0f;
    float4 o = reinterpret_cast<float4*>(out)[t];
    uint2 vv = reinterpret_cast<const uint2*>(g_vh)[t];
    float2 v01 = __half22float2(*reinterpret_cast<__half2*>(&vv.x));
    float2 v23 = __half22float2(*reinterpret_cast<__half2*>(&vv.y));
    o.x = v01.x + o.x * sc;
    o.y = v01.y + o.y * sc;
    o.z = v23.x + o.z * sc;
    o.w = v23.y + o.w * sc;
    reinterpret_cast<float4*>(out)[t] = o;
}

// ---------------------------------------------------------------------------
extern "C" void kernel_launch(void* const* d_in, const int* in_sizes, int n_in,
                              void* d_out, int out_size)
{
    const float* x   = (const float*)d_in[0];
    const float* Wq0 = (const float*)d_in[1];
    const float* Wq1 = (const float*)d_in[2];
    const float* Wq2 = (const float*)d_in[3];
    const float* Wk0 = (const float*)d_in[4];
    const float* Wk1 = (const float*)d_in[5];
    const float* Wk2 = (const float*)d_in[6];
    const float* Wv0 = (const float*)d_in[7];
    const float* Wv1 = (const float*)d_in[8];
    const float* Wv2 = (const float*)d_in[9];
    const float* Wd0 = (const float*)d_in[10];
    const float* Wd1 = (const float*)d_in[11];
    const float* Wd2 = (const float*)d_in[12];
    const int* edge_dst = (const int*)d_in[13];
    const int* edge_src = (const int*)d_in[14];
    float* out = (float*)d_out;

    // Node kernel: 16 nodes/block (2 per warp), 50000/16 = 3125 blocks
    node_kernel<<<NNODES / 16, 256>>>(x, Wq0, Wq1, Wq2, Wk0, Wk1, Wk2,
                                      Wv0, Wv1, Wv2, Wd0, Wd1, Wd2, out);

    // Fused edge kernel: 16 edges/block (one warp each), 50000 blocks exactly
    edge_kernel<<<NEDGES / 16, 512>>>(edge_dst, edge_src, out);

    // Finalize: one thread per float4 of out
    const int nt = NNODES * (FEAT / 4);
    finalize_kernel<<<(nt + 255) / 256, 256>>>(out);
}